// round 7
// baseline (speedup 1.0000x reference)
#include <cuda_runtime.h>

#define NN 8192
#define DD 128
#define PP 256
#define KK 256
#define DEG 32
#define FF 16
#define INV_TEMP (1.0f / 0.07f)
#define FULL 0xffffffffu
#define RPAD 132   // 128 floats + 4 pad -> conflict-free transposed LDS.128

// Scratch (__device__ globals; no allocations allowed)
__device__ float g_t1[PP], g_t2[PP], g_posc[PP], g_neg[KK];
__device__ int   g_count = 0;

__device__ __forceinline__ float warp_sum(float v) {
#pragma unroll
    for (int o = 16; o; o >>= 1) v += __shfl_xor_sync(FULL, v, o);
    return v;
}

__device__ __forceinline__ float dot4(float4 a, float4 b) {
    return a.x * b.x + a.y * b.y + a.z * b.z + a.w * b.w;
}

// ---------------------------------------------------------------------------
// Grid = PP = 256 blocks x 96 threads (3 warps). Block b handles neighbor i=b.
//   warp0: term1  (rows = N(q), ref = z_i)   -- one LANE per row (DEG==32)
//   warp1: term2  (rows = N(i), ref = z_q)   -- one lane per row
//   warp2: norms of z_q/z_i/z_neg (one 5-var butterfly) + mu_xy/pos/core/neg
// Rows staged coalesced GMEM->SMEM (pad RPAD), then each lane dots its own
// row serially (conflict-free LDS) -> mu_j in lane j -> softmax is a plain
// in-warp reduction. No cross-warp coupling except the norm handoff.
// Align loss (term1+term2) computed by the last-arriving block.
// ---------------------------------------------------------------------------
__global__ void __launch_bounds__(96)
fused_kernel(const float* __restrict__ z,
             const float* __restrict__ et,
             const float* __restrict__ ct,
             const float* __restrict__ core,
             const float* __restrict__ omega,
             const float* __restrict__ phi,
             const int* __restrict__ qidx,
             const int* __restrict__ neg_idxs,
             const int* __restrict__ nbr_idxs,
             const int* __restrict__ neighbors,
             float* __restrict__ out) {
    __shared__ float s_rows[2][DEG * RPAD];
    __shared__ float s_ref[2][DD];
    __shared__ int   s_idx[2][DEG];
    __shared__ float s_nm[4];            // rq, aq, ri, ai
    __shared__ float s_ws[3];
    __shared__ bool  s_isLast;

    const int t = threadIdx.x, lane = t & 31, warp = t >> 5;
    const int i = blockIdx.x;

    const int   q   = qidx[0];
    const int   nbr = nbr_idxs[i];
    const float ct0 = ct[0];

    float nr = 0.f, dr = 0.f, mydt = 0.f;

    if (warp < 2) {
        const int base   = (warp == 0) ? q : nbr;   // whose neighborhood
        const int refRow = (warp == 0) ? nbr : q;   // vector dotted vs rows

        // lane's row index + edge time (scattered, issued early)
        const int myIdx = neighbors[base * DEG + lane];
        s_idx[warp][lane] = myIdx;
        mydt = ct0 - et[(long long)base * NN + myIdx];

        // ref row -> smem (coalesced)
        ((float4*)s_ref[warp])[lane] =
            ((const float4*)(z + (long long)refRow * DD))[lane];
        __syncwarp();

        // stage all 32 rows coalesced (4 wavefronts/row)
#pragma unroll 8
        for (int j = 0; j < DEG; j++) {
            const int rj = s_idx[warp][j];
            const float4 v = ((const float4*)(z + (long long)rj * DD))[lane];
            *(float4*)&s_rows[warp][j * RPAD + lane * 4] = v;
        }
        __syncwarp();

        // lane = row: serial dot over own row (transposed LDS, conflict-free)
#pragma unroll 8
        for (int c = 0; c < DD / 4; c++) {
            const float4 rv = *(const float4*)&s_rows[warp][lane * RPAD + 4 * c];
            const float4 fv = ((const float4*)s_ref[warp])[c];   // broadcast
            nr += dot4(rv, rv);
            dr += dot4(fv, rv);
        }
    } else {
        // ---- warp2: norms + extras ----
        float cq = 0.f, ci = 0.f;
        if (lane == 0) { cq = core[q]; ci = core[nbr]; }
        const int negy = neg_idxs[i];
        const float4 zq4 = ((const float4*)(z + (long long)q    * DD))[lane];
        const float4 zi4 = ((const float4*)(z + (long long)nbr  * DD))[lane];
        const float4 zn4 = ((const float4*)(z + (long long)negy * DD))[lane];
        float nq  = dot4(zq4, zq4), ni = dot4(zi4, zi4), nn = dot4(zn4, zn4);
        float dqi = dot4(zq4, zi4), dqn = dot4(zq4, zn4);
#pragma unroll
        for (int o = 16; o; o >>= 1) {
            nq  += __shfl_xor_sync(FULL, nq,  o);
            ni  += __shfl_xor_sync(FULL, ni,  o);
            nn  += __shfl_xor_sync(FULL, nn,  o);
            dqi += __shfl_xor_sync(FULL, dqi, o);
            dqn += __shfl_xor_sync(FULL, dqn, o);
        }
        const float rq = rsqrtf(fmaxf(nq, 1e-24f)), aq = nq * rq * rq;
        const float ri = rsqrtf(fmaxf(ni, 1e-24f)), ai = ni * ri * ri;
        if (lane == 0) {
            s_nm[0] = rq; s_nm[1] = aq; s_nm[2] = ri; s_nm[3] = ai;
            // pos + core losses
            const float mu_xy = -(aq + ai - 2.f * rq * ri * dqi);
            const float sg = 1.f / (1.f + __expf(-mu_xy));
            const float dc = ci - cq;
            g_posc[i] = -__logf(sg + 1e-8f) * (1.f / PP)
                      + (0.1f / PP) * dc * dc;
        } else if (lane == 1) {
            // negative loss
            const float rn = rsqrtf(fmaxf(nn, 1e-24f));
            const float an = nn * rn * rn;
            const float mu = -(aq + an - 2.f * rq * rn * dqn);
            const float sg = 1.f / (1.f + __expf(-mu));
            g_neg[i] = -__logf(1.f - sg + 1e-8f) * (1.f / KK);
        }
    }

    __syncthreads();   // norms published; rows/dots done

    if (warp < 2) {
        // time encoding for this lane's row
        float te = omega[0] * mydt + phi[0];
#pragma unroll
        for (int f = 1; f < FF; f++) te += __sinf(omega[f] * mydt + phi[f]);

        const float rref = (warp == 0) ? s_nm[2] : s_nm[0];
        const float aref = (warp == 0) ? s_nm[3] : s_nm[1];
        const float rr = rsqrtf(fmaxf(nr, 1e-24f));
        const float mu = -(aref + nr * rr * rr - 2.f * rref * rr * dr);

        // softmax over lanes (= over the 32 rows), exact reference formula
        const float w = __expf(mu * INV_TEMP - te);
        const float S = warp_sum(w);
        const float a = w / (S + 1e-8f);
        const float term = warp_sum(a * mu);
        if (lane == 0) {
            if (warp == 0) g_t1[i] = term;
            else           g_t2[i] = term;
        }
    }

    // ---- completion: last-arriving block computes align + total ----
    __threadfence();
    __syncthreads();
    if (t == 0) {
        const int c = atomicAdd(&g_count, 1);
        s_isLast = (c == (int)gridDim.x - 1);
    }
    __syncthreads();
    if (s_isLast) {
        __threadfence();
        float sv = 0.f;
        for (int idx = t; idx < PP; idx += 96) {
            const float dd = g_t1[idx] + g_t2[idx];   // lambda_T - lambda_S
            const float ad = fabsf(dd);
            const float al = (ad < 1.f) ? 0.5f * dd * dd : (ad - 0.5f);
            sv += g_posc[idx] + g_neg[idx] + al * (0.1f / PP);
        }
        sv = warp_sum(sv);
        if (lane == 0) s_ws[warp] = sv;
        __syncthreads();
        if (t == 0) {
            out[0] = s_ws[0] + s_ws[1] + s_ws[2];
            g_count = 0;   // reset for next graph replay
        }
    }
}

// ---------------------------------------------------------------------------
// Inputs (metadata order):
// 0 z [N*D] f32, 1 edge_times [N*N] f32, 2 current_time [1] f32,
// 3 core_values [N] f32, 4 omega [F] f32, 5 phi [F] f32,
// 6 query_idx [1] i32, 7 neg_idxs [K] i32, 8 neighbor_idxs [P] i32,
// 9 neighbors [N*DEG] i32. Output: [1] f32.
// ---------------------------------------------------------------------------
extern "C" void kernel_launch(void* const* d_in, const int* in_sizes, int n_in,
                              void* d_out, int out_size) {
    const float* z     = (const float*)d_in[0];
    const float* et    = (const float*)d_in[1];
    const float* ct    = (const float*)d_in[2];
    const float* core  = (const float*)d_in[3];
    const float* omega = (const float*)d_in[4];
    const float* phi   = (const float*)d_in[5];
    const int*   qidx  = (const int*)d_in[6];
    const int*   negi  = (const int*)d_in[7];
    const int*   nbri  = (const int*)d_in[8];
    const int*   nbrs  = (const int*)d_in[9];

    fused_kernel<<<PP, 96>>>(z, et, ct, core, omega, phi,
                             qidx, negi, nbri, nbrs, (float*)d_out);
}

// round 10
// speedup vs baseline: 1.4673x; 1.4673x over previous
#include <cuda_runtime.h>

#define NN 8192
#define DD 128
#define PP 256
#define KK 256
#define DEG 32
#define FF 16
#define INV_TEMP (1.0f / 0.07f)
#define FULL 0xffffffffu

// Scratch (__device__ globals; no allocations allowed)
__device__ float g_t1[PP], g_t2[PP], g_posc[PP], g_neg[KK];
__device__ int   g_count = 0;

__device__ __forceinline__ float warp_sum(float v) {
#pragma unroll
    for (int o = 16; o; o >>= 1) v += __shfl_xor_sync(FULL, v, o);
    return v;
}

__device__ __forceinline__ float dot4(float4 a, float4 b) {
    return a.x * b.x + a.y * b.y + a.z * b.z + a.w * b.w;
}

// ---------------------------------------------------------------------------
// Grid = 2*PP = 512 blocks x 256 threads (8 warps).
//   block b in [0,PP):   term1 for neighbor i=b (+ mu_xy/pos/core in warp 0)
//   block b in [PP,2PP): term2 for neighbor i=b-PP (+ negative in warp 0)
// Warp w owns rows 4w..4w+3 (indices via ONE uniform int4 load — no shfl on
// the load path). Row warps publish raw (nr, dr) partial-reduction results;
// warp 0 finishes mu (needs aref/rref it computes once) and does the softmax.
// Align loss (term1+term2) computed by the last-arriving block.
// ---------------------------------------------------------------------------
__global__ void __launch_bounds__(256)
fused_kernel(const float* __restrict__ z,
             const float* __restrict__ et,
             const float* __restrict__ ct,
             const float* __restrict__ core,
             const float* __restrict__ omega,
             const float* __restrict__ phi,
             const int* __restrict__ qidx,
             const int* __restrict__ neg_idxs,
             const int* __restrict__ nbr_idxs,
             const int* __restrict__ neighbors,
             float* __restrict__ out) {
    __shared__ float s_nr[DEG], s_dr[DEG], s_te[DEG];
    __shared__ float s_ws[8];
    __shared__ bool  s_isLast;

    const int t = threadIdx.x, lane = t & 31, warp = t >> 5;
    const int b = blockIdx.x;
    const bool isT1 = (b < PP);
    const int  i = isT1 ? b : b - PP;

    // ---- level-0 scalars (broadcast loads) ----
    const int   q   = qidx[0];
    const int   nbr = nbr_idxs[i];
    const float ct0 = ct[0];
    const int   baseRow = isT1 ? q : nbr;   // whose neighborhood
    const int   refRow  = isT1 ? nbr : q;   // vector dotted against rows

    float cq = 0.f, ci = 0.f;
    if (isT1 && t == 0) { cq = core[q]; ci = core[nbr]; }

    // ---- level-1: 4 row indices via ONE uniform LDG.128 (no shfl chain) ----
    const int4 ii4 = ((const int4*)(neighbors + baseRow * DEG))[warp];
    const float4* refp = (const float4*)(z + (long long)refRow * DD);
    const float4 ref4 = refp[lane];

    // warp0 aux row: T1 -> z_q (mu_xy) ; T2 -> z_neg (negative loss)
    float4 aux4 = make_float4(0.f, 0.f, 0.f, 0.f);
    if (warp == 0) {
        const int auxRow = isT1 ? q : neg_idxs[i];
        aux4 = ((const float4*)(z + (long long)auxRow * DD))[lane];
    }

    // ---- level-2: the 4 rows (immediately after index load) + edge times ----
    const float4 r0 = ((const float4*)(z + (long long)ii4.x * DD))[lane];
    const float4 r1 = ((const float4*)(z + (long long)ii4.y * DD))[lane];
    const float4 r2 = ((const float4*)(z + (long long)ii4.z * DD))[lane];
    const float4 r3 = ((const float4*)(z + (long long)ii4.w * DD))[lane];
    float mydt = 0.f;
    if (lane < 4) {
        const int myRow = (lane & 2) ? ((lane & 1) ? ii4.w : ii4.z)
                                     : ((lane & 1) ? ii4.y : ii4.x);
        mydt = ct0 - et[(long long)baseRow * NN + myRow];
    }

    // ---- time encodings: 8 lanes per dt (4 dts per warp) ----
    {
        const int g = lane >> 3, sub = lane & 7;
        const float dtv = __shfl_sync(FULL, mydt, g);
        float p = __sinf(omega[1 + sub] * dtv + phi[1 + sub]);
        if (sub < 7) p += __sinf(omega[9 + sub] * dtv + phi[9 + sub]);
        p += __shfl_xor_sync(FULL, p, 1);
        p += __shfl_xor_sync(FULL, p, 2);
        p += __shfl_xor_sync(FULL, p, 4);
        if (sub == 0) s_te[4 * warp + g] = omega[0] * dtv + phi[0] + p;
    }

    // ---- row partials: publish raw (nr, dr); mu finished by warp 0 later ----
    {
        const float n0 = warp_sum(dot4(r0, r0)), d0 = warp_sum(dot4(ref4, r0));
        const float n1 = warp_sum(dot4(r1, r1)), d1 = warp_sum(dot4(ref4, r1));
        const float n2 = warp_sum(dot4(r2, r2)), d2 = warp_sum(dot4(ref4, r2));
        const float n3 = warp_sum(dot4(r3, r3)), d3 = warp_sum(dot4(ref4, r3));
        if (lane == 0) {
            const int j = 4 * warp;
            s_nr[j] = n0; s_dr[j] = d0;
            s_nr[j + 1] = n1; s_dr[j + 1] = d1;
            s_nr[j + 2] = n2; s_dr[j + 2] = d2;
            s_nr[j + 3] = n3; s_dr[j + 3] = d3;
        }
    }

    // ---- warp 0: ref/aux norms + extras (mu_xy/pos/core or negative) ----
    float aref = 0.f, rref = 0.f;
    if (warp == 0) {
        const float nf = warp_sum(dot4(ref4, ref4));
        const float na = warp_sum(dot4(aux4, aux4));
        const float da = warp_sum(dot4(aux4, ref4));
        rref = rsqrtf(fmaxf(nf, 1e-24f));
        aref = nf * rref * rref;                 // ||ref_hat||^2
        const float ra = rsqrtf(fmaxf(na, 1e-24f));
        const float aa = na * ra * ra;
        const float mu = -(aa + aref - 2.f * ra * rref * da);
        if (lane == 0) {
            if (isT1) {
                // mu here = mu_xy (aux = z_q, ref = z_i)
                const float sg = 1.f / (1.f + __expf(-mu));
                const float dc = ci - cq;
                g_posc[i] = -__logf(sg + 1e-8f) * (1.f / PP)
                          + (0.1f / PP) * dc * dc;
            } else {
                // mu here = neg mu (aux = z_neg, ref = z_q)
                const float sg = 1.f / (1.f + __expf(-mu));
                g_neg[i] = -__logf(1.f - sg + 1e-8f) * (1.f / KK);
            }
        }
    }
    __syncthreads();  // publish s_nr/s_dr/s_te

    // ---- softmax in warp 0 (has aref/rref), exact reference formula ----
    if (warp == 0) {
        const float nr = s_nr[lane], dr = s_dr[lane];
        const float rr = rsqrtf(fmaxf(nr, 1e-24f));
        const float mu = -(aref + nr * rr * rr - 2.f * rref * rr * dr);
        const float w = __expf(mu * INV_TEMP - s_te[lane]);
        const float S = warp_sum(w);
        const float a = w / (S + 1e-8f);
        const float term = warp_sum(a * mu);
        if (lane == 0) {
            if (isT1) g_t1[i] = term;
            else      g_t2[i] = term;
        }
    }

    // ---- completion: last-arriving block computes align + total ----
    __threadfence();
    __syncthreads();
    if (t == 0) {
        const int c = atomicAdd(&g_count, 1);
        s_isLast = (c == (int)gridDim.x - 1);
    }
    __syncthreads();
    if (s_isLast) {
        __threadfence();
        const float dd = g_t1[t] + g_t2[t];      // lambda_T - lambda_S
        const float ad = fabsf(dd);
        const float al = (ad < 1.f) ? 0.5f * dd * dd : (ad - 0.5f);
        float sv = g_posc[t] + g_neg[t] + al * (0.1f / PP);
        sv = warp_sum(sv);
        if (lane == 0) s_ws[warp] = sv;
        __syncthreads();
        if (t == 0) {
            float tot = 0.f;
#pragma unroll
            for (int w = 0; w < 8; w++) tot += s_ws[w];
            out[0] = tot;
            g_count = 0;   // reset for next graph replay
        }
    }
}

// ---------------------------------------------------------------------------
// Inputs (metadata order):
// 0 z [N*D] f32, 1 edge_times [N*N] f32, 2 current_time [1] f32,
// 3 core_values [N] f32, 4 omega [F] f32, 5 phi [F] f32,
// 6 query_idx [1] i32, 7 neg_idxs [K] i32, 8 neighbor_idxs [P] i32,
// 9 neighbors [N*DEG] i32. Output: [1] f32.
// ---------------------------------------------------------------------------
extern "C" void kernel_launch(void* const* d_in, const int* in_sizes, int n_in,
                              void* d_out, int out_size) {
    const float* z     = (const float*)d_in[0];
    const float* et    = (const float*)d_in[1];
    const float* ct    = (const float*)d_in[2];
    const float* core  = (const float*)d_in[3];
    const float* omega = (const float*)d_in[4];
    const float* phi   = (const float*)d_in[5];
    const int*   qidx  = (const int*)d_in[6];
    const int*   negi  = (const int*)d_in[7];
    const int*   nbri  = (const int*)d_in[8];
    const int*   nbrs  = (const int*)d_in[9];

    fused_kernel<<<2 * PP, 256>>>(z, et, ct, core, omega, phi,
                                  qidx, negi, nbri, nbrs, (float*)d_out);
}

// round 11
// speedup vs baseline: 1.6643x; 1.1343x over previous
#include <cuda_runtime.h>

#define NN 8192
#define DD 128
#define PP 256
#define KK 256
#define DEG 32
#define FF 16
#define INV_TEMP (1.0f / 0.07f)
#define FULL 0xffffffffu

// Scratch (__device__ globals; no allocations allowed)
__device__ float g_t1[PP], g_t2[PP], g_posc[PP], g_neg[KK];
__device__ int   g_count = 0;

__device__ __forceinline__ float warp_sum(float v) {
#pragma unroll
    for (int o = 16; o; o >>= 1) v += __shfl_xor_sync(FULL, v, o);
    return v;
}

__device__ __forceinline__ float dot4(float4 a, float4 b) {
    return a.x * b.x + a.y * b.y + a.z * b.z + a.w * b.w;
}

// ---------------------------------------------------------------------------
// Grid = 2*PP = 512 blocks x 256 threads (8 warps).
//   block b in [0,PP):   term1 for neighbor i=b (+ mu_xy/pos/core in warp 0)
//   block b in [PP,2PP): term2 for neighbor i=b-PP (+ negative in warp 0)
// Warp w owns rows 4w..4w+3 (indices via ONE uniform int4 load). Row warps
// publish raw (nr, dr); warp 0 finishes mu and does the softmax with the
// numerator/denominator reduced as two INTERLEAVED chains (5 shfl levels,
// not 10). Edge-time loads are 8-lane broadcast LDGs (no dt shuffle).
// Align loss (term1+term2) computed by the last-arriving block.
// ---------------------------------------------------------------------------
__global__ void __launch_bounds__(256)
fused_kernel(const float* __restrict__ z,
             const float* __restrict__ et,
             const float* __restrict__ ct,
             const float* __restrict__ core,
             const float* __restrict__ omega,
             const float* __restrict__ phi,
             const int* __restrict__ qidx,
             const int* __restrict__ neg_idxs,
             const int* __restrict__ nbr_idxs,
             const int* __restrict__ neighbors,
             float* __restrict__ out) {
    __shared__ float s_nr[DEG], s_dr[DEG], s_te[DEG];
    __shared__ float s_ws[8];
    __shared__ bool  s_isLast;

    const int t = threadIdx.x, lane = t & 31, warp = t >> 5;
    const int b = blockIdx.x;
    const bool isT1 = (b < PP);
    const int  i = isT1 ? b : b - PP;

    // ---- level-0 scalars (broadcast loads) ----
    const int   q   = qidx[0];
    const int   nbr = nbr_idxs[i];
    const float ct0 = ct[0];
    const int   baseRow = isT1 ? q : nbr;   // whose neighborhood
    const int   refRow  = isT1 ? nbr : q;   // vector dotted against rows

    float cq = 0.f, ci = 0.f;
    if (isT1 && t == 0) { cq = core[q]; ci = core[nbr]; }

    // ---- level-1: 4 row indices via ONE uniform LDG.128 (no shfl chain) ----
    const int4 ii4 = ((const int4*)(neighbors + baseRow * DEG))[warp];
    const float4 ref4 = ((const float4*)(z + (long long)refRow * DD))[lane];

    // warp0 aux row: T1 -> z_q (mu_xy) ; T2 -> z_neg (negative loss)
    float4 aux4 = make_float4(0.f, 0.f, 0.f, 0.f);
    if (warp == 0) {
        const int auxRow = isT1 ? q : neg_idxs[i];
        aux4 = ((const float4*)(z + (long long)auxRow * DD))[lane];
    }

    // ---- level-2: the 4 rows + edge time (ii4 is warp-uniform, so every
    // lane selects its 8-lane group's row directly; broadcast LDG) ----
    const int g = lane >> 3, sub = lane & 7;
    const int gRow = (g & 2) ? ((g & 1) ? ii4.w : ii4.z)
                             : ((g & 1) ? ii4.y : ii4.x);
    const float4 r0 = ((const float4*)(z + (long long)ii4.x * DD))[lane];
    const float4 r1 = ((const float4*)(z + (long long)ii4.y * DD))[lane];
    const float4 r2 = ((const float4*)(z + (long long)ii4.z * DD))[lane];
    const float4 r3 = ((const float4*)(z + (long long)ii4.w * DD))[lane];
    const float dtv = ct0 - et[(long long)baseRow * NN + gRow];

    // ---- time encoding: 8 lanes per dt, 2 sinusoid slots per lane ----
    {
        float p = __sinf(omega[1 + sub] * dtv + phi[1 + sub]);
        p += (sub < 7) ? __sinf(omega[9 + sub] * dtv + phi[9 + sub])
                       : (omega[0] * dtv + phi[0]);
        p += __shfl_xor_sync(FULL, p, 1);
        p += __shfl_xor_sync(FULL, p, 2);
        p += __shfl_xor_sync(FULL, p, 4);
        if (sub == 0) s_te[4 * warp + g] = p;
    }

    // ---- row partials: 8 independent interleaved reduction chains ----
    {
        float n0 = dot4(r0, r0), d0 = dot4(ref4, r0);
        float n1 = dot4(r1, r1), d1 = dot4(ref4, r1);
        float n2 = dot4(r2, r2), d2 = dot4(ref4, r2);
        float n3 = dot4(r3, r3), d3 = dot4(ref4, r3);
#pragma unroll
        for (int o = 16; o; o >>= 1) {
            n0 += __shfl_xor_sync(FULL, n0, o);
            d0 += __shfl_xor_sync(FULL, d0, o);
            n1 += __shfl_xor_sync(FULL, n1, o);
            d1 += __shfl_xor_sync(FULL, d1, o);
            n2 += __shfl_xor_sync(FULL, n2, o);
            d2 += __shfl_xor_sync(FULL, d2, o);
            n3 += __shfl_xor_sync(FULL, n3, o);
            d3 += __shfl_xor_sync(FULL, d3, o);
        }
        if (lane == 0) {
            const int j = 4 * warp;
            s_nr[j] = n0; s_dr[j] = d0;
            s_nr[j + 1] = n1; s_dr[j + 1] = d1;
            s_nr[j + 2] = n2; s_dr[j + 2] = d2;
            s_nr[j + 3] = n3; s_dr[j + 3] = d3;
        }
    }

    // ---- warp 0: ref/aux norms (3 interleaved chains) + extras ----
    float aref = 0.f, rref = 0.f;
    if (warp == 0) {
        float nf = dot4(ref4, ref4);
        float na = dot4(aux4, aux4);
        float da = dot4(aux4, ref4);
#pragma unroll
        for (int o = 16; o; o >>= 1) {
            nf += __shfl_xor_sync(FULL, nf, o);
            na += __shfl_xor_sync(FULL, na, o);
            da += __shfl_xor_sync(FULL, da, o);
        }
        rref = rsqrtf(fmaxf(nf, 1e-24f));
        aref = nf * rref * rref;                 // ||ref_hat||^2
        const float ra = rsqrtf(fmaxf(na, 1e-24f));
        const float aa = na * ra * ra;
        const float mu = -(aa + aref - 2.f * ra * rref * da);
        if (lane == 0) {
            const float sg = 1.f / (1.f + __expf(-mu));
            if (isT1) {
                // mu = mu_xy (aux = z_q, ref = z_i)
                const float dc = ci - cq;
                g_posc[i] = -__logf(sg + 1e-8f) * (1.f / PP)
                          + (0.1f / PP) * dc * dc;
            } else {
                // mu = negative-sample mu (aux = z_neg, ref = z_q)
                g_neg[i] = -__logf(1.f - sg + 1e-8f) * (1.f / KK);
            }
        }
    }
    __syncthreads();  // publish s_nr/s_dr/s_te

    // ---- softmax in warp 0: numerator & denominator as TWO interleaved
    // chains; term = Sum(w*mu) / (Sum(w) + 1e-8)  (== ref formula) ----
    if (warp == 0) {
        const float nr = s_nr[lane], dr = s_dr[lane];
        const float rr = rsqrtf(fmaxf(nr, 1e-24f));
        const float mu = -(aref + nr * rr * rr - 2.f * rref * rr * dr);
        float w  = __expf(mu * INV_TEMP - s_te[lane]);
        float wm = w * mu;
#pragma unroll
        for (int o = 16; o; o >>= 1) {
            w  += __shfl_xor_sync(FULL, w,  o);
            wm += __shfl_xor_sync(FULL, wm, o);
        }
        if (lane == 0) {
            const float term = wm / (w + 1e-8f);
            if (isT1) g_t1[i] = term;
            else      g_t2[i] = term;
        }
    }

    // ---- completion: last-arriving block computes align + total ----
    __threadfence();
    __syncthreads();
    if (t == 0) {
        const int c = atomicAdd(&g_count, 1);
        s_isLast = (c == (int)gridDim.x - 1);
    }
    __syncthreads();
    if (s_isLast) {
        __threadfence();
        const float dd = g_t1[t] + g_t2[t];      // lambda_T - lambda_S
        const float ad = fabsf(dd);
        const float al = (ad < 1.f) ? 0.5f * dd * dd : (ad - 0.5f);
        float sv = g_posc[t] + g_neg[t] + al * (0.1f / PP);
        sv = warp_sum(sv);
        if (lane == 0) s_ws[warp] = sv;
        __syncthreads();
        if (t == 0) {
            float tot = 0.f;
#pragma unroll
            for (int w = 0; w < 8; w++) tot += s_ws[w];
            out[0] = tot;
            g_count = 0;   // reset for next graph replay
        }
    }
}

// ---------------------------------------------------------------------------
// Inputs (metadata order):
// 0 z [N*D] f32, 1 edge_times [N*N] f32, 2 current_time [1] f32,
// 3 core_values [N] f32, 4 omega [F] f32, 5 phi [F] f32,
// 6 query_idx [1] i32, 7 neg_idxs [K] i32, 8 neighbor_idxs [P] i32,
// 9 neighbors [N*DEG] i32. Output: [1] f32.
// ---------------------------------------------------------------------------
extern "C" void kernel_launch(void* const* d_in, const int* in_sizes, int n_in,
                              void* d_out, int out_size) {
    const float* z     = (const float*)d_in[0];
    const float* et    = (const float*)d_in[1];
    const float* ct    = (const float*)d_in[2];
    const float* core  = (const float*)d_in[3];
    const float* omega = (const float*)d_in[4];
    const float* phi   = (const float*)d_in[5];
    const int*   qidx  = (const int*)d_in[6];
    const int*   negi  = (const int*)d_in[7];
    const int*   nbri  = (const int*)d_in[8];
    const int*   nbrs  = (const int*)d_in[9];

    fused_kernel<<<2 * PP, 256>>>(z, et, ct, core, omega, phi,
                                  qidx, negi, nbri, nbrs, (float*)d_out);
}